// round 1
// baseline (speedup 1.0000x reference)
#include <cuda_runtime.h>
#include <cstdint>

// DCNv2 specialization:
//   input  : [8][9][160][160] f32     (b_in, ct, h, w)
//   weight : [3][3][48][3]    f32     (kh, kw, cout, cg)
//   offset : [16][3][2]       f32     (b_out, g, {y,x})
//   output : [16][48][160][160] f32
//
// Key fact: sampling offsets depend only on (b,g,k) -> constant fractional
// shift per plane. Per (b,g): stage 3 input channels into SMEM with halo,
// each pixel computes 27 bilinear samples (shared corner rows across 4
// vertically-contiguous pixels per thread), then out[16] = W[16x27] @ s[27].

namespace {
constexpr int Hdim = 160;
constexpr int Wdim = 160;
constexpr int TILE = 32;
constexpr int HALO = 5;                 // floor(dy) in [-4,4] -> rows i-4..i+5
constexpr int SMW  = TILE + 2 * HALO;   // 42
constexpr int THREADS = 256;
constexpr int OPG = 16;                 // out channels per group
}

__global__ __launch_bounds__(THREADS, 2)
void dcn_kernel(const float* __restrict__ input,
                const float* __restrict__ weight,
                const float* __restrict__ offset,
                float* __restrict__ out)
{
    const int bg = blockIdx.z;          // 0..47
    const int b  = bg / 3;              // 0..15
    const int g  = bg % 3;              // 0..2
    const int tile_x = blockIdx.x * TILE;
    const int tile_y = blockIdx.y * TILE;

    __shared__ float sm[3][SMW][SMW];   // input tile, 3 channels, zero-padded halo
    __shared__ float wsm[OPG][27];      // wsm[o][c*9+k]
    __shared__ float s_wy[9], s_wx[9];
    __shared__ int   s_fy[9], s_fx[9];

    const int tid = threadIdx.x;

    // ---- per-k shift constants (9 threads) ----
    if (tid < 9) {
        const float offy = offset[(b * 3 + g) * 2 + 0];
        const float offx = offset[(b * 3 + g) * 2 + 1];
        const float py = (float)(tid / 3 - 1);
        const float px = (float)(tid % 3 - 1);
        const float dy = py * (1.0f + 3.0f / offy);
        const float dx = px * (1.0f + 3.0f / offx);
        const float fy = floorf(dy);
        const float fx = floorf(dx);
        s_fy[tid] = (int)fy;
        s_fx[tid] = (int)fx;
        s_wy[tid] = dy - fy;
        s_wx[tid] = dx - fx;
    }

    // ---- weights: wmat[g][o][c][k] = weight[k*144 + (g*16+o)*3 + c] ----
    for (int i = tid; i < OPG * 27; i += THREADS) {
        const int o  = i / 27;
        const int ck = i % 27;
        const int c  = ck / 9;
        const int k  = ck % 9;
        wsm[o][ck] = weight[k * 144 + (g * OPG + o) * 3 + c];
    }

    // ---- stage input tile (+halo, zero pad outside image) ----
    // input batch = b >> 1 (num_p = 2), channel = g*3 + c
    const float* inb = input + (size_t)(b >> 1) * 9 * Hdim * Wdim;
    for (int i = tid; i < 3 * SMW * SMW; i += THREADS) {
        const int c = i / (SMW * SMW);
        const int r = (i / SMW) % SMW;
        const int q = i % SMW;
        const int gy = tile_y + r - HALO;
        const int gx = tile_x + q - HALO;
        float v = 0.0f;
        if (gy >= 0 && gy < Hdim && gx >= 0 && gx < Wdim)
            v = inb[(size_t)(g * 3 + c) * Hdim * Wdim + gy * Wdim + gx];
        sm[c][r][q] = v;
    }
    __syncthreads();

    // ---- compute: thread = 1 column x 4 contiguous rows ----
    const int tx = tid & 31;            // column within tile
    const int r0 = (tid >> 5) * 4;      // first of 4 rows

    float acc[OPG][4];
    #pragma unroll
    for (int o = 0; o < OPG; o++)
        #pragma unroll
        for (int p = 0; p < 4; p++)
            acc[o][p] = 0.0f;

    #pragma unroll 1
    for (int k = 0; k < 9; k++) {
        const int   fy = s_fy[k];
        const int   fx = s_fx[k];
        const float wy = s_wy[k];
        const float wx = s_wx[k];

        #pragma unroll
        for (int c = 0; c < 3; c++) {
            const float* base = &sm[c][r0 + HALO + fy][tx + HALO + fx];

            // 5 corner rows, 2 columns -> 10 LDS for 4 pixels
            float s[4];
            float ap = base[0];
            float bp = base[1];
            #pragma unroll
            for (int p = 0; p < 4; p++) {
                const float an = base[(p + 1) * SMW];
                const float bn = base[(p + 1) * SMW + 1];
                const float v0 = fmaf(wy, an - ap, ap);
                const float v1 = fmaf(wy, bn - bp, bp);
                s[p] = fmaf(wx, v1 - v0, v0);
                ap = an;
                bp = bn;
            }

            const int ck = c * 9 + k;
            #pragma unroll
            for (int o = 0; o < OPG; o++) {
                const float wv = wsm[o][ck];
                #pragma unroll
                for (int p = 0; p < 4; p++)
                    acc[o][p] = fmaf(s[p], wv, acc[o][p]);
            }
        }
    }

    // ---- store: out[b][g*16+o][i][j] ----
    float* outp = out + (size_t)(b * 48 + g * OPG) * Hdim * Wdim
                      + (size_t)(tile_y + r0) * Wdim + tile_x + tx;
    #pragma unroll
    for (int o = 0; o < OPG; o++) {
        #pragma unroll
        for (int p = 0; p < 4; p++)
            outp[(size_t)o * Hdim * Wdim + p * Wdim] = acc[o][p];
    }
}

extern "C" void kernel_launch(void* const* d_in, const int* in_sizes, int n_in,
                              void* d_out, int out_size)
{
    const float* input  = (const float*)d_in[0];
    const float* weight = (const float*)d_in[1];
    const float* offset = (const float*)d_in[2];
    float* out = (float*)d_out;

    dim3 grid(Wdim / TILE, Hdim / TILE, 48);   // 5 x 5 x 48
    dcn_kernel<<<grid, THREADS>>>(input, weight, offset, out);
}